// round 7
// baseline (speedup 1.0000x reference)
#include <cuda_runtime.h>

#define B_ 128
#define N_ 1024
#define E_ 16384
#define ENTITY_ 100000
#define HID_ 100
#define G3 300

// Scratch (static __device__ per harness rules; no runtime allocation)
__device__ float g_T[ENTITY_ * HID_];        // emb_table @ gcn_w   (40MB)
__device__ float g_seq[B_ * N_ * HID_];      // GCN output          (52MB)
__device__ float g_GX[B_ * N_ * G3];         // seq @ w_ih^T + b_ih (157MB)
__device__ int   g_soff[B_ * (N_ + 1)];
__device__ int   g_scol[B_ * E_];
__device__ float g_sval[B_ * E_];

typedef unsigned long long u64;
typedef unsigned int u32;

__device__ __forceinline__ void ffma2(u64 &acc, u64 a, u64 b) {
    asm("fma.rn.f32x2 %0, %1, %2, %0;" : "+l"(acc) : "l"(a), "l"(b));
}
__device__ __forceinline__ float sum2(u64 v) {
    float lo, hi; asm("mov.b64 {%0, %1}, %2;" : "=f"(lo), "=f"(hi) : "l"(v)); return lo + hi;
}
__device__ __forceinline__ void cp4(void* s, const void* g) {
    unsigned a = (unsigned)__cvta_generic_to_shared(s);
    asm volatile("cp.async.ca.shared.global [%0], [%1], 4;" :: "r"(a), "l"(g));
}
__device__ __forceinline__ u32 f2tf(float x) {
    u32 r; asm("cvt.rna.tf32.f32 %0, %1;" : "=r"(r) : "f"(x)); return r;
}
__device__ __forceinline__ void mma1688(float c[4], u32 a0, u32 a1, u32 a2, u32 a3,
                                        u32 b0, u32 b1) {
    asm("mma.sync.aligned.m16n8k8.row.col.f32.tf32.tf32.f32 "
        "{%0,%1,%2,%3}, {%4,%5,%6,%7}, {%8,%9}, {%0,%1,%2,%3};"
        : "+f"(c[0]), "+f"(c[1]), "+f"(c[2]), "+f"(c[3])
        : "r"(a0), "r"(a1), "r"(a2), "r"(a3), "r"(b0), "r"(b1));
}

// ---------------------------------------------------------------------------
// tf32 GEMM: out[M x NOUT] = X[M x 100] @ W^T (+ bias if HASB)
// W given [NOUT x 100] row-major if !TRANSW, or [100 x NOUT] k-major if TRANSW.
// 512 threads = 16 warps (4 m-pos x 4 n-groups); block tile 64 x NP.
// NSPLIT: column-split factor. Each block owns cols [ch*NP, ch*NP+NP) with
// ch = blockIdx.x % NSPLIT -> smem small enough for 2 blocks/SM (occupancy).
// W staged once in smem as [n][k], stride KP=108 (conflict-free frag loads).
// K=100 padded to 104 -> 13 k-steps of m16n8k8.
// ---------------------------------------------------------------------------
#define KP 108

template<int NP, int NFR, int NOUT, int NSPLIT, bool TRANSW, bool USE_GSEQ, bool HASB>
__global__ __launch_bounds__(512, 2) void gemm_tf32(const float* __restrict__ Xparam,
                                                    const float* __restrict__ Wg,
                                                    const float* __restrict__ bias,
                                                    int Mtotal, int ntiles) {
    extern __shared__ u32 smem[];
    u32* Ws = smem;                                  // NP * KP
    u32* Xs = smem + NP * KP;                        // 64 * KP
    float* bs = (float*)(smem + NP * KP + 64 * KP);  // NP

    const float* X = USE_GSEQ ? (const float*)g_seq : Xparam;
    float* out = USE_GSEQ ? (float*)g_GX : (float*)g_T;

    int tid = threadIdx.x;
    int w = tid >> 5, lane = tid & 31;
    int mw = w & 3, nw = w >> 2;
    int g = lane >> 2, tig = lane & 3;
    int colbase = nw * NFR * 8;

    int ch = (NSPLIT == 2) ? (int)(blockIdx.x & 1) : 0;
    int colOff = ch * NP;
    int tile0 = blockIdx.x / NSPLIT;
    int tstride = gridDim.x / NSPLIT;

    // --- Stage W (once per block) ---
    if (TRANSW) {
        for (int i = tid; i < NP * KP; i += 512) {
            int n = i / KP, k = i % KP;
            int gc = colOff + n;
            float v = (gc < NOUT && k < HID_) ? Wg[k * NOUT + gc] : 0.f;
            Ws[n * KP + k] = f2tf(v);
        }
    } else {
        for (int i = tid; i < NP * 27; i += 512) {
            int n = i / 27, c = i % 27;
            int gc = colOff + n;
            float4 v = make_float4(0.f, 0.f, 0.f, 0.f);
            if (gc < NOUT && c < 25) v = ((const float4*)Wg)[gc * 25 + c];
            u32* d = Ws + n * KP + c * 4;
            d[0] = f2tf(v.x); d[1] = f2tf(v.y); d[2] = f2tf(v.z); d[3] = f2tf(v.w);
        }
    }
    for (int i = tid; i < NP; i += 512)
        bs[i] = (HASB && colOff + i < NOUT) ? bias[colOff + i] : 0.f;
    __syncthreads();

    const int ncols = (NOUT - colOff < NP) ? (NOUT - colOff) : NP;   // divisible by 4
    const int nc4 = ncols / 4;

    for (int tile = tile0; tile < ntiles; tile += tstride) {
        __syncthreads();   // previous tile's Xs fully consumed
        for (int i = tid; i < 64 * 27; i += 512) {
            int m = i / 27, c = i % 27;
            int row = tile * 64 + m;
            float4 v = make_float4(0.f, 0.f, 0.f, 0.f);
            if (row < Mtotal && c < 25) v = ((const float4*)X)[(size_t)row * 25 + c];
            u32* d = Xs + m * KP + c * 4;
            d[0] = f2tf(v.x); d[1] = f2tf(v.y); d[2] = f2tf(v.z); d[3] = f2tf(v.w);
        }
        __syncthreads();

        float c[NFR][4];
        #pragma unroll
        for (int f = 0; f < NFR; f++) { c[f][0] = 0.f; c[f][1] = 0.f; c[f][2] = 0.f; c[f][3] = 0.f; }

        const u32* Xb = Xs + (mw * 16) * KP;
        #pragma unroll
        for (int ks = 0; ks < 13; ks++) {
            int k0 = ks * 8;
            u32 a0 = Xb[g * KP + k0 + tig];
            u32 a1 = Xb[(g + 8) * KP + k0 + tig];
            u32 a2 = Xb[g * KP + k0 + tig + 4];
            u32 a3 = Xb[(g + 8) * KP + k0 + tig + 4];
            #pragma unroll
            for (int f = 0; f < NFR; f++) {
                const u32* wp = Ws + (colbase + 8 * f + g) * KP + k0 + tig;
                u32 b0 = wp[0];
                u32 b1 = wp[4];
                mma1688(c[f], a0, a1, a2, a3, b0, b1);
            }
        }

        int r0 = tile * 64 + mw * 16 + g;
        #pragma unroll
        for (int f = 0; f < NFR; f++) {
            int col = colOff + colbase + 8 * f + 2 * tig;
            if (r0 < Mtotal) {
                if (col < NOUT)     out[(size_t)r0 * NOUT + col]     = c[f][0] + bs[col - colOff];
                if (col + 1 < NOUT) out[(size_t)r0 * NOUT + col + 1] = c[f][1] + bs[col + 1 - colOff];
            }
            if (r0 + 8 < Mtotal) {
                if (col < NOUT)     out[(size_t)(r0 + 8) * NOUT + col]     = c[f][2] + bs[col - colOff];
                if (col + 1 < NOUT) out[(size_t)(r0 + 8) * NOUT + col + 1] = c[f][3] + bs[col + 1 - colOff];
            }
        }
    }
    (void)nc4;
}

#define K1_SMEM ((128 * KP + 64 * KP) * 4 + 128 * 4)
#define K4_SMEM ((160 * KP + 64 * KP) * 4 + 160 * 4)

// ---------------------------------------------------------------------------
// K2: per-batch counting sort of edges by row (histogram + scan + scatter)
// ---------------------------------------------------------------------------
__global__ __launch_bounds__(1024) void k2_sort(const int* __restrict__ row,
                                                const int* __restrict__ col,
                                                const float* __restrict__ val) {
    __shared__ int bins[N_];
    __shared__ int sA[N_];
    int b = blockIdx.x, tid = threadIdx.x;
    bins[tid] = 0;
    __syncthreads();
    const int* rb = row + b * E_;
    const int* cb = col + b * E_;
    const float* vb = val + b * E_;
    for (int e = tid; e < E_; e += 1024) atomicAdd(&bins[rb[e]], 1);
    __syncthreads();
    int cnt = bins[tid];
    sA[tid] = cnt;
    __syncthreads();
    for (int off = 1; off < N_; off <<= 1) {
        int t = (tid >= off) ? sA[tid - off] : 0;
        __syncthreads();
        sA[tid] += t;
        __syncthreads();
    }
    int excl = sA[tid] - cnt;
    g_soff[b * (N_ + 1) + tid] = excl;
    if (tid == 0) g_soff[b * (N_ + 1) + N_] = E_;
    bins[tid] = excl;
    __syncthreads();
    for (int e = tid; e < E_; e += 1024) {
        int r = rb[e];
        int pos = atomicAdd(&bins[r], 1);
        g_scol[b * E_ + pos] = cb[e];
        g_sval[b * E_ + pos] = vb[e];
    }
}

// ---------------------------------------------------------------------------
// K3: seq[b,r,:] = sum_e val * T[neighbors[b, col_e], :] + gcn_b
// one warp per (b, row); 4-edge unroll (MLP=16)  [R5 version — proven]
// ---------------------------------------------------------------------------
__global__ __launch_bounds__(256) void k3_agg(const int* __restrict__ nbr,
                                              const float* __restrict__ gcn_b) {
    int b = blockIdx.x;
    int rbase = blockIdx.y * 64;
    int warp = threadIdx.x >> 5, lane = threadIdx.x & 31;
    const int* sc = g_scol + b * E_;
    const float* sv = g_sval + b * E_;
    const int* nb = nbr + b * N_;
    for (int r = rbase + warp; r < rbase + 64; r += 8) {
        int beg = g_soff[b * (N_ + 1) + r], end = g_soff[b * (N_ + 1) + r + 1];
        float a0 = 0.f, a1 = 0.f, a2 = 0.f, a3 = 0.f;
        float c0 = 0.f, c1 = 0.f, c2 = 0.f, c3 = 0.f;
        for (int ch = beg; ch < end; ch += 32) {
            int e = ch + lane;
            int c = 0; float v = 0.f;
            if (e < end) { c = sc[e]; v = sv[e]; }
            int ent = nb[c];
            int cnt = min(32, end - ch);
            int i = 0;
            for (; i + 3 < cnt; i += 4) {
                int e0 = __shfl_sync(0xffffffffu, ent, i);
                int e1 = __shfl_sync(0xffffffffu, ent, i + 1);
                int e2 = __shfl_sync(0xffffffffu, ent, i + 2);
                int e3 = __shfl_sync(0xffffffffu, ent, i + 3);
                float v0 = __shfl_sync(0xffffffffu, v, i);
                float v1 = __shfl_sync(0xffffffffu, v, i + 1);
                float v2 = __shfl_sync(0xffffffffu, v, i + 2);
                float v3 = __shfl_sync(0xffffffffu, v, i + 3);
                const float* t0 = g_T + (size_t)e0 * HID_;
                const float* t1 = g_T + (size_t)e1 * HID_;
                const float* t2 = g_T + (size_t)e2 * HID_;
                const float* t3 = g_T + (size_t)e3 * HID_;
                float x00 = t0[lane], x01 = t0[32 + lane], x02 = t0[64 + lane], x03 = t0[96 + (lane & 3)];
                float x10 = t1[lane], x11 = t1[32 + lane], x12 = t1[64 + lane], x13 = t1[96 + (lane & 3)];
                float x20 = t2[lane], x21 = t2[32 + lane], x22 = t2[64 + lane], x23 = t2[96 + (lane & 3)];
                float x30 = t3[lane], x31 = t3[32 + lane], x32 = t3[64 + lane], x33 = t3[96 + (lane & 3)];
                a0 += v0 * x00; a1 += v0 * x01; a2 += v0 * x02; a3 += v0 * x03;
                c0 += v1 * x10; c1 += v1 * x11; c2 += v1 * x12; c3 += v1 * x13;
                a0 += v2 * x20; a1 += v2 * x21; a2 += v2 * x22; a3 += v2 * x23;
                c0 += v3 * x30; c1 += v3 * x31; c2 += v3 * x32; c3 += v3 * x33;
            }
            for (; i < cnt; i++) {
                int e0 = __shfl_sync(0xffffffffu, ent, i);
                float v0 = __shfl_sync(0xffffffffu, v, i);
                const float* t0 = g_T + (size_t)e0 * HID_;
                a0 += v0 * t0[lane];
                a1 += v0 * t0[32 + lane];
                a2 += v0 * t0[64 + lane];
                a3 += v0 * t0[96 + (lane & 3)];
            }
        }
        float* o = g_seq + (size_t)(b * N_ + r) * HID_;
        o[lane]      = a0 + c0 + gcn_b[lane];
        o[32 + lane] = a1 + c1 + gcn_b[32 + lane];
        o[64 + lane] = a2 + c2 + gcn_b[64 + lane];
        if (lane < 4) o[96 + lane] = a3 + c3 + gcn_b[96 + lane];
    }
}

// ---------------------------------------------------------------------------
// K5: GRU recurrence, one block per batch element; fast MUFU activations.
// ---------------------------------------------------------------------------
__global__ __launch_bounds__(320) void k5_gru(const float* __restrict__ w_hh,
                                              const float* __restrict__ b_hh,
                                              const float* __restrict__ fc1_w,
                                              const float* __restrict__ fc1_b,
                                              float* __restrict__ out) {
    __shared__ __align__(16) float hbuf[2][128];
    __shared__ float ghs[G3];
    __shared__ float ring[8][G3];
    int b = blockIdx.x, tid = threadIdx.x;
    int j = tid;
    bool act = j < G3;
    u64 w2[50];
    float bhh = 0.f;
    if (act) {
        const u64* wp = (const u64*)(w_hh + j * HID_);
        #pragma unroll
        for (int p = 0; p < 50; p++) w2[p] = wp[p];
        bhh = b_hh[j];
    }
    if (tid < 128) { hbuf[0][tid] = 0.f; hbuf[1][tid] = 0.f; }
    const float* gxb = g_GX + (size_t)b * N_ * G3;
    #pragma unroll
    for (int p = 0; p < 4; p++) {
        if (act) cp4(&ring[p][j], gxb + p * G3 + j);
        asm volatile("cp.async.commit_group;");
    }
    for (int t = 0; t < N_; t++) {
        asm volatile("cp.async.wait_group 3;");
        __syncthreads();
        int pf = t + 4;
        if (act && pf < N_) cp4(&ring[pf & 7][j], gxb + (size_t)pf * G3 + j);
        asm volatile("cp.async.commit_group;");
        const float* hc = hbuf[t & 1];
        if (act) {
            const ulonglong2* hp = (const ulonglong2*)hc;
            u64 a0 = 0, a1 = 0, a2 = 0, a3 = 0;
            #pragma unroll
            for (int qq = 0; qq < 25; qq++) {
                ulonglong2 hv = hp[qq];
                if (qq & 1) { ffma2(a2, w2[2 * qq], hv.x); ffma2(a3, w2[2 * qq + 1], hv.y); }
                else        { ffma2(a0, w2[2 * qq], hv.x); ffma2(a1, w2[2 * qq + 1], hv.y); }
            }
            ghs[j] = sum2(a0) + sum2(a1) + sum2(a2) + sum2(a3) + bhh;
        }
        __syncthreads();
        if (j < HID_) {
            int st = t & 7;
            float gxr = ring[st][j], gxz = ring[st][HID_ + j], gxn = ring[st][2 * HID_ + j];
            float hr = ghs[j], hz = ghs[HID_ + j], hn = ghs[2 * HID_ + j];
            float er = __expf(-(gxr + hr));
            float r = __fdividef(1.f, 1.f + er);
            float ez = __expf(-(gxz + hz));
            float z = __fdividef(1.f, 1.f + ez);
            float an = gxn + r * hn;
            float e2 = __expf(2.f * an);
            float n = 1.f - __fdividef(2.f, e2 + 1.f);
            hbuf[(t + 1) & 1][j] = (1.f - z) * n + z * hc[j];
        }
    }
    __syncthreads();
    if (j < HID_) {
        const float* hf = hbuf[0];
        float acc = fc1_b[j];
        const float* wr = fc1_w + j * HID_;
        #pragma unroll
        for (int k = 0; k < HID_; k++) acc += hf[k] * wr[k];
        out[b * HID_ + j] = fmaxf(acc, 0.f);
    }
}

// ---------------------------------------------------------------------------
extern "C" void kernel_launch(void* const* d_in, const int* in_sizes, int n_in,
                              void* d_out, int out_size) {
    const int*   neighbors = (const int*)d_in[0];
    const int*   adj_row   = (const int*)d_in[1];
    const int*   adj_col   = (const int*)d_in[2];
    const float* adj_val   = (const float*)d_in[3];
    const float* emb       = (const float*)d_in[4];
    const float* gcn_w     = (const float*)d_in[5];
    const float* gcn_b     = (const float*)d_in[6];
    const float* w_ih      = (const float*)d_in[7];
    const float* w_hh      = (const float*)d_in[8];
    const float* b_ih      = (const float*)d_in[9];
    const float* b_hh      = (const float*)d_in[10];
    const float* fc1_w     = (const float*)d_in[11];
    const float* fc1_b     = (const float*)d_in[12];
    float* out = (float*)d_out;

    cudaFuncSetAttribute(gemm_tf32<128, 4, 100, 1, true, false, false>,
                         cudaFuncAttributeMaxDynamicSharedMemorySize, K1_SMEM);
    cudaFuncSetAttribute(gemm_tf32<160, 5, 300, 2, false, true, true>,
                         cudaFuncAttributeMaxDynamicSharedMemorySize, K4_SMEM);

    // K1: T = emb @ gcn_w  (no bias — gcn_b is added in K3 after the spmm)
    gemm_tf32<128, 4, 100, 1, true, false, false><<<148, 512, K1_SMEM>>>(
        emb, gcn_w, gcn_b, ENTITY_, (ENTITY_ + 63) / 64);
    k2_sort<<<B_, 1024>>>(adj_row, adj_col, adj_val);
    k3_agg <<<dim3(B_, 16), 256>>>(neighbors, gcn_b);
    // K4: GX = seq @ w_ih^T + b_ih  (column-split x2 for occupancy)
    gemm_tf32<160, 5, 300, 2, false, true, true><<<296, 512, K4_SMEM>>>(
        nullptr, w_ih, b_ih, B_ * N_, (B_ * N_ + 63) / 64);
    k5_gru <<<B_, 320>>>(w_hh, b_hh, fc1_w, fc1_b, out);
}

// round 8
// speedup vs baseline: 1.5922x; 1.5922x over previous
#include <cuda_runtime.h>

#define B_ 128
#define N_ 1024
#define E_ 16384
#define ENTITY_ 100000
#define HID_ 100
#define G3 300

// Scratch (static __device__ per harness rules; no runtime allocation)
__device__ float g_T[ENTITY_ * HID_];        // emb_table @ gcn_w   (40MB)
__device__ float g_seq[B_ * N_ * HID_];      // GCN output          (52MB)
__device__ float g_GX[B_ * N_ * G3];         // seq @ w_ih^T + b_ih (157MB)
__device__ int   g_soff[B_ * (N_ + 1)];
__device__ int   g_scol[B_ * E_];
__device__ float g_sval[B_ * E_];

typedef unsigned long long u64;
typedef unsigned int u32;

__device__ __forceinline__ void ffma2(u64 &acc, u64 a, u64 b) {
    asm("fma.rn.f32x2 %0, %1, %2, %0;" : "+l"(acc) : "l"(a), "l"(b));
}
__device__ __forceinline__ float sum2(u64 v) {
    float lo, hi; asm("mov.b64 {%0, %1}, %2;" : "=f"(lo), "=f"(hi) : "l"(v)); return lo + hi;
}
__device__ __forceinline__ void cp4(void* s, const void* g) {
    unsigned a = (unsigned)__cvta_generic_to_shared(s);
    asm volatile("cp.async.ca.shared.global [%0], [%1], 4;" :: "r"(a), "l"(g));
}
__device__ __forceinline__ u32 f2tf(float x) {
    u32 r; asm("cvt.rna.tf32.f32 %0, %1;" : "=r"(r) : "f"(x)); return r;
}
__device__ __forceinline__ float tanhapx(float x) {
    float r; asm("tanh.approx.f32 %0, %1;" : "=f"(r) : "f"(x)); return r;
}
__device__ __forceinline__ void mma1688(float c[4], u32 a0, u32 a1, u32 a2, u32 a3,
                                        u32 b0, u32 b1) {
    asm("mma.sync.aligned.m16n8k8.row.col.f32.tf32.tf32.f32 "
        "{%0,%1,%2,%3}, {%4,%5,%6,%7}, {%8,%9}, {%0,%1,%2,%3};"
        : "+f"(c[0]), "+f"(c[1]), "+f"(c[2]), "+f"(c[3])
        : "r"(a0), "r"(a1), "r"(a2), "r"(a3), "r"(b0), "r"(b1));
}

// ---------------------------------------------------------------------------
// tf32 GEMM: out[M x NOUT] = X[M x 100] @ W^T (+ bias if HASB)   [R5 structure]
// 512 threads = 16 warps (4 m-pos x 4 n-groups); block tile 64 x NP; W staged
// once per block; K padded to 104 = 13 k-steps of m16n8k8.
// k-PAIRED smem layout: within each 8-k group, k sits at 8*ks + 2*(k&3) +
// ((k&7)>>2), so the two k-halves of every fragment are adjacent 8 bytes ->
// all a/b fragment loads are single LDS.64 (halves inner-loop LDS count).
// KP=104: bank(u32) = (8g + 2*tig) per half-warp phase -> conflict-free.
// ---------------------------------------------------------------------------
#define KP 104

__device__ __forceinline__ int kidx(int k) {   // paired index within a row
    return ((k >> 3) << 3) + ((k & 3) << 1) + ((k & 7) >> 2);
}

template<int NP, int NFR, int NOUT, bool TRANSW, bool USE_GSEQ, bool HASB>
__global__ __launch_bounds__(512) void gemm_tf32(const float* __restrict__ Xparam,
                                                 const float* __restrict__ Wg,
                                                 const float* __restrict__ bias,
                                                 int Mtotal, int ntiles) {
    extern __shared__ u32 smem[];
    u32* Ws = smem;                                  // NP * KP
    u32* Xs = smem + NP * KP;                        // 64 * KP
    float* bs = (float*)(smem + NP * KP + 64 * KP);  // NP

    const float* X = USE_GSEQ ? (const float*)g_seq : Xparam;
    float* out = USE_GSEQ ? (float*)g_GX : (float*)g_T;

    int tid = threadIdx.x;
    int w = tid >> 5, lane = tid & 31;
    int mw = w & 3, nw = w >> 2;
    int g = lane >> 2, tig = lane & 3;
    int colbase = nw * NFR * 8;

    // --- Stage W (once per block), generic element loop with paired layout ---
    for (int i = tid; i < NP * KP; i += 512) {
        int n = i / KP, k = i % KP;
        float v = 0.f;
        if (n < NOUT && k < HID_)
            v = TRANSW ? Wg[k * NOUT + n] : Wg[n * HID_ + k];
        Ws[n * KP + kidx(k)] = f2tf(v);
    }
    for (int i = tid; i < NP; i += 512)
        bs[i] = (HASB && i < NOUT) ? bias[i] : 0.f;
    __syncthreads();

    for (int tile = blockIdx.x; tile < ntiles; tile += gridDim.x) {
        __syncthreads();   // previous tile's Xs fully consumed
        // X staging: float4 gmem reads, scattered STS into paired layout.
        // c in [0,25): data; c == 25: zero-fill the k=100..103 slots.
        for (int i = tid; i < 64 * 26; i += 512) {
            int m = i / 26, c = i % 26;
            u32* rowp = Xs + m * KP;
            if (c < 25) {
                int row = tile * 64 + m;
                float4 v = make_float4(0.f, 0.f, 0.f, 0.f);
                if (row < Mtotal) v = ((const float4*)X)[(size_t)row * 25 + c];
                int base = ((c >> 1) << 3) + (c & 1);
                rowp[base]     = f2tf(v.x);
                rowp[base + 2] = f2tf(v.y);
                rowp[base + 4] = f2tf(v.z);
                rowp[base + 6] = f2tf(v.w);
            } else {
                // k = 100..103 -> paired indices 97, 99, 101, 103
                rowp[97] = 0u; rowp[99] = 0u; rowp[101] = 0u; rowp[103] = 0u;
            }
        }
        __syncthreads();

        float c[NFR][4];
        #pragma unroll
        for (int f = 0; f < NFR; f++) { c[f][0] = 0.f; c[f][1] = 0.f; c[f][2] = 0.f; c[f][3] = 0.f; }

        const u32* Xb = Xs + (mw * 16) * KP;
        #pragma unroll
        for (int ks = 0; ks < 13; ks++) {
            int k0 = ks * 8 + 2 * tig;
            uint2 pa0 = *(const uint2*)&Xb[g * KP + k0];          // (a0, a2)
            uint2 pa1 = *(const uint2*)&Xb[(g + 8) * KP + k0];    // (a1, a3)
            #pragma unroll
            for (int f = 0; f < NFR; f++) {
                uint2 pb = *(const uint2*)&Ws[(colbase + 8 * f + g) * KP + k0];  // (b0, b1)
                mma1688(c[f], pa0.x, pa1.x, pa0.y, pa1.y, pb.x, pb.y);
            }
        }

        int r0 = tile * 64 + mw * 16 + g;
        #pragma unroll
        for (int f = 0; f < NFR; f++) {
            int col = colbase + 8 * f + 2 * tig;
            if (r0 < Mtotal) {
                if (col < NOUT)     out[(size_t)r0 * NOUT + col]     = c[f][0] + bs[col];
                if (col + 1 < NOUT) out[(size_t)r0 * NOUT + col + 1] = c[f][1] + bs[col + 1];
            }
            if (r0 + 8 < Mtotal) {
                if (col < NOUT)     out[(size_t)(r0 + 8) * NOUT + col]     = c[f][2] + bs[col];
                if (col + 1 < NOUT) out[(size_t)(r0 + 8) * NOUT + col + 1] = c[f][3] + bs[col + 1];
            }
        }
    }
}

#define K1_SMEM ((128 * KP + 64 * KP) * 4 + 128 * 4)
#define K4_SMEM ((320 * KP + 64 * KP) * 4 + 320 * 4)

// ---------------------------------------------------------------------------
// K2: per-batch counting sort of edges by row (histogram + scan + scatter)
// ---------------------------------------------------------------------------
__global__ __launch_bounds__(1024) void k2_sort(const int* __restrict__ row,
                                                const int* __restrict__ col,
                                                const float* __restrict__ val) {
    __shared__ int bins[N_];
    __shared__ int sA[N_];
    int b = blockIdx.x, tid = threadIdx.x;
    bins[tid] = 0;
    __syncthreads();
    const int* rb = row + b * E_;
    const int* cb = col + b * E_;
    const float* vb = val + b * E_;
    for (int e = tid; e < E_; e += 1024) atomicAdd(&bins[rb[e]], 1);
    __syncthreads();
    int cnt = bins[tid];
    sA[tid] = cnt;
    __syncthreads();
    for (int off = 1; off < N_; off <<= 1) {
        int t = (tid >= off) ? sA[tid - off] : 0;
        __syncthreads();
        sA[tid] += t;
        __syncthreads();
    }
    int excl = sA[tid] - cnt;
    g_soff[b * (N_ + 1) + tid] = excl;
    if (tid == 0) g_soff[b * (N_ + 1) + N_] = E_;
    bins[tid] = excl;
    __syncthreads();
    for (int e = tid; e < E_; e += 1024) {
        int r = rb[e];
        int pos = atomicAdd(&bins[r], 1);
        g_scol[b * E_ + pos] = cb[e];
        g_sval[b * E_ + pos] = vb[e];
    }
}

// ---------------------------------------------------------------------------
// K3: seq[b,r,:] = sum_e val * T[neighbors[b, col_e], :] + gcn_b
// one warp per (b, row); 4-edge unroll (MLP=16)  [R5 version — proven]
// ---------------------------------------------------------------------------
__global__ __launch_bounds__(256) void k3_agg(const int* __restrict__ nbr,
                                              const float* __restrict__ gcn_b) {
    int b = blockIdx.x;
    int rbase = blockIdx.y * 64;
    int warp = threadIdx.x >> 5, lane = threadIdx.x & 31;
    const int* sc = g_scol + b * E_;
    const float* sv = g_sval + b * E_;
    const int* nb = nbr + b * N_;
    for (int r = rbase + warp; r < rbase + 64; r += 8) {
        int beg = g_soff[b * (N_ + 1) + r], end = g_soff[b * (N_ + 1) + r + 1];
        float a0 = 0.f, a1 = 0.f, a2 = 0.f, a3 = 0.f;
        float c0 = 0.f, c1 = 0.f, c2 = 0.f, c3 = 0.f;
        for (int ch = beg; ch < end; ch += 32) {
            int e = ch + lane;
            int c = 0; float v = 0.f;
            if (e < end) { c = sc[e]; v = sv[e]; }
            int ent = nb[c];
            int cnt = min(32, end - ch);
            int i = 0;
            for (; i + 3 < cnt; i += 4) {
                int e0 = __shfl_sync(0xffffffffu, ent, i);
                int e1 = __shfl_sync(0xffffffffu, ent, i + 1);
                int e2 = __shfl_sync(0xffffffffu, ent, i + 2);
                int e3 = __shfl_sync(0xffffffffu, ent, i + 3);
                float v0 = __shfl_sync(0xffffffffu, v, i);
                float v1 = __shfl_sync(0xffffffffu, v, i + 1);
                float v2 = __shfl_sync(0xffffffffu, v, i + 2);
                float v3 = __shfl_sync(0xffffffffu, v, i + 3);
                const float* t0 = g_T + (size_t)e0 * HID_;
                const float* t1 = g_T + (size_t)e1 * HID_;
                const float* t2 = g_T + (size_t)e2 * HID_;
                const float* t3 = g_T + (size_t)e3 * HID_;
                float x00 = t0[lane], x01 = t0[32 + lane], x02 = t0[64 + lane], x03 = t0[96 + (lane & 3)];
                float x10 = t1[lane], x11 = t1[32 + lane], x12 = t1[64 + lane], x13 = t1[96 + (lane & 3)];
                float x20 = t2[lane], x21 = t2[32 + lane], x22 = t2[64 + lane], x23 = t2[96 + (lane & 3)];
                float x30 = t3[lane], x31 = t3[32 + lane], x32 = t3[64 + lane], x33 = t3[96 + (lane & 3)];
                a0 += v0 * x00; a1 += v0 * x01; a2 += v0 * x02; a3 += v0 * x03;
                c0 += v1 * x10; c1 += v1 * x11; c2 += v1 * x12; c3 += v1 * x13;
                a0 += v2 * x20; a1 += v2 * x21; a2 += v2 * x22; a3 += v2 * x23;
                c0 += v3 * x30; c1 += v3 * x31; c2 += v3 * x32; c3 += v3 * x33;
            }
            for (; i < cnt; i++) {
                int e0 = __shfl_sync(0xffffffffu, ent, i);
                float v0 = __shfl_sync(0xffffffffu, v, i);
                const float* t0 = g_T + (size_t)e0 * HID_;
                a0 += v0 * t0[lane];
                a1 += v0 * t0[32 + lane];
                a2 += v0 * t0[64 + lane];
                a3 += v0 * t0[96 + (lane & 3)];
            }
        }
        float* o = g_seq + (size_t)(b * N_ + r) * HID_;
        o[lane]      = a0 + c0 + gcn_b[lane];
        o[32 + lane] = a1 + c1 + gcn_b[32 + lane];
        o[64 + lane] = a2 + c2 + gcn_b[64 + lane];
        if (lane < 4) o[96 + lane] = a3 + c3 + gcn_b[96 + lane];
    }
}

// ---------------------------------------------------------------------------
// K5: GRU recurrence, one block per batch element; HW tanh.approx activations.
// ---------------------------------------------------------------------------
__global__ __launch_bounds__(320) void k5_gru(const float* __restrict__ w_hh,
                                              const float* __restrict__ b_hh,
                                              const float* __restrict__ fc1_w,
                                              const float* __restrict__ fc1_b,
                                              float* __restrict__ out) {
    __shared__ __align__(16) float hbuf[2][128];
    __shared__ float ghs[G3];
    __shared__ float ring[8][G3];
    int b = blockIdx.x, tid = threadIdx.x;
    int j = tid;
    bool act = j < G3;
    u64 w2[50];
    float bhh = 0.f;
    if (act) {
        const u64* wp = (const u64*)(w_hh + j * HID_);
        #pragma unroll
        for (int p = 0; p < 50; p++) w2[p] = wp[p];
        bhh = b_hh[j];
    }
    if (tid < 128) { hbuf[0][tid] = 0.f; hbuf[1][tid] = 0.f; }
    const float* gxb = g_GX + (size_t)b * N_ * G3;
    #pragma unroll
    for (int p = 0; p < 4; p++) {
        if (act) cp4(&ring[p][j], gxb + p * G3 + j);
        asm volatile("cp.async.commit_group;");
    }
    for (int t = 0; t < N_; t++) {
        asm volatile("cp.async.wait_group 3;");
        __syncthreads();
        int pf = t + 4;
        if (act && pf < N_) cp4(&ring[pf & 7][j], gxb + (size_t)pf * G3 + j);
        asm volatile("cp.async.commit_group;");
        const float* hc = hbuf[t & 1];
        if (act) {
            const ulonglong2* hp = (const ulonglong2*)hc;
            u64 a0 = 0, a1 = 0, a2 = 0, a3 = 0;
            #pragma unroll
            for (int qq = 0; qq < 25; qq++) {
                ulonglong2 hv = hp[qq];
                if (qq & 1) { ffma2(a2, w2[2 * qq], hv.x); ffma2(a3, w2[2 * qq + 1], hv.y); }
                else        { ffma2(a0, w2[2 * qq], hv.x); ffma2(a1, w2[2 * qq + 1], hv.y); }
            }
            ghs[j] = sum2(a0) + sum2(a1) + sum2(a2) + sum2(a3) + bhh;
        }
        __syncthreads();
        if (j < HID_) {
            int st = t & 7;
            float gxr = ring[st][j], gxz = ring[st][HID_ + j], gxn = ring[st][2 * HID_ + j];
            float hr = ghs[j], hz = ghs[HID_ + j], hn = ghs[2 * HID_ + j];
            float r = 0.5f * tanhapx(0.5f * (gxr + hr)) + 0.5f;
            float z = 0.5f * tanhapx(0.5f * (gxz + hz)) + 0.5f;
            float n = tanhapx(gxn + r * hn);
            hbuf[(t + 1) & 1][j] = (1.f - z) * n + z * hc[j];
        }
    }
    __syncthreads();
    if (j < HID_) {
        const float* hf = hbuf[0];
        float acc = fc1_b[j];
        const float* wr = fc1_w + j * HID_;
        #pragma unroll
        for (int k = 0; k < HID_; k++) acc += hf[k] * wr[k];
        out[b * HID_ + j] = fmaxf(acc, 0.f);
    }
}

// ---------------------------------------------------------------------------
extern "C" void kernel_launch(void* const* d_in, const int* in_sizes, int n_in,
                              void* d_out, int out_size) {
    const int*   neighbors = (const int*)d_in[0];
    const int*   adj_row   = (const int*)d_in[1];
    const int*   adj_col   = (const int*)d_in[2];
    const float* adj_val   = (const float*)d_in[3];
    const float* emb       = (const float*)d_in[4];
    const float* gcn_w     = (const float*)d_in[5];
    const float* gcn_b     = (const float*)d_in[6];
    const float* w_ih      = (const float*)d_in[7];
    const float* w_hh      = (const float*)d_in[8];
    const float* b_ih      = (const float*)d_in[9];
    const float* b_hh      = (const float*)d_in[10];
    const float* fc1_w     = (const float*)d_in[11];
    const float* fc1_b     = (const float*)d_in[12];
    float* out = (float*)d_out;

    cudaFuncSetAttribute(gemm_tf32<128, 4, 100, true, false, false>,
                         cudaFuncAttributeMaxDynamicSharedMemorySize, K1_SMEM);
    cudaFuncSetAttribute(gemm_tf32<320, 10, 300, false, true, true>,
                         cudaFuncAttributeMaxDynamicSharedMemorySize, K4_SMEM);

    // K1: T = emb @ gcn_w  (no bias — gcn_b is added in K3 after the spmm)
    gemm_tf32<128, 4, 100, true, false, false><<<148, 512, K1_SMEM>>>(
        emb, gcn_w, gcn_b, ENTITY_, (ENTITY_ + 63) / 64);
    k2_sort<<<B_, 1024>>>(adj_row, adj_col, adj_val);
    k3_agg <<<dim3(B_, 16), 256>>>(neighbors, gcn_b);
    // K4: GX = seq @ w_ih^T + b_ih
    gemm_tf32<320, 10, 300, false, true, true><<<148, 512, K4_SMEM>>>(
        nullptr, w_ih, b_ih, B_ * N_, (B_ * N_ + 63) / 64);
    k5_gru <<<B_, 320>>>(w_hh, b_hh, fc1_w, fc1_b, out);
}

// round 9
// speedup vs baseline: 1.6511x; 1.0370x over previous
#include <cuda_runtime.h>

#define B_ 128
#define N_ 1024
#define E_ 16384
#define ENTITY_ 100000
#define HID_ 100
#define G3 300

// Scratch (static __device__ per harness rules; no runtime allocation)
__device__ float g_T[ENTITY_ * HID_];        // emb_table @ gcn_w   (40MB)
__device__ float g_seq[B_ * N_ * HID_];      // GCN output          (52MB)
__device__ float g_GX[B_ * N_ * G3];         // seq @ w_ih^T + b_ih (157MB)
__device__ int   g_soff[B_ * (N_ + 1)];
__device__ int   g_scol[B_ * E_];
__device__ float g_sval[B_ * E_];

typedef unsigned long long u64;
typedef unsigned int u32;

__device__ __forceinline__ void ffma2(u64 &acc, u64 a, u64 b) {
    asm("fma.rn.f32x2 %0, %1, %2, %0;" : "+l"(acc) : "l"(a), "l"(b));
}
__device__ __forceinline__ float sum2(u64 v) {
    float lo, hi; asm("mov.b64 {%0, %1}, %2;" : "=f"(lo), "=f"(hi) : "l"(v)); return lo + hi;
}
__device__ __forceinline__ void cp4(void* s, const void* g) {
    unsigned a = (unsigned)__cvta_generic_to_shared(s);
    asm volatile("cp.async.ca.shared.global [%0], [%1], 4;" :: "r"(a), "l"(g));
}
__device__ __forceinline__ u32 f2tf(float x) {
    u32 r; asm("cvt.rna.tf32.f32 %0, %1;" : "=r"(r) : "f"(x)); return r;
}
__device__ __forceinline__ float tanhapx(float x) {
    float r; asm("tanh.approx.f32 %0, %1;" : "=f"(r) : "f"(x)); return r;
}
__device__ __forceinline__ void mma1688(float c[4], u32 a0, u32 a1, u32 a2, u32 a3,
                                        u32 b0, u32 b1) {
    asm("mma.sync.aligned.m16n8k8.row.col.f32.tf32.tf32.f32 "
        "{%0,%1,%2,%3}, {%4,%5,%6,%7}, {%8,%9}, {%0,%1,%2,%3};"
        : "+f"(c[0]), "+f"(c[1]), "+f"(c[2]), "+f"(c[3])
        : "r"(a0), "r"(a1), "r"(a2), "r"(a3), "r"(b0), "r"(b1));
}

// ---------------------------------------------------------------------------
// tf32 GEMM: out[M x NOUT] = X[M x 100] @ W^T (+ bias if HASB)
// M-tile = 128 rows (each warp covers TWO 16-row m-blocks -> every W-fragment
// LDS.64 feeds 2 MMAs, halving smem-crossbar pressure vs the 64-row tile).
// 512 threads = 16 warps (4 m-pos x 4 n-groups). W staged once per block.
// k-PAIRED smem layout (k at 8*ks + 2*(k&3) + ((k&7)>>2)): all fragment
// loads are single LDS.64. KP=104, conflict-free.
// ---------------------------------------------------------------------------
#define KP 104

__device__ __forceinline__ int kidx(int k) {   // paired index within a row
    return ((k >> 3) << 3) + ((k & 3) << 1) + ((k & 7) >> 2);
}

template<int NP, int NFR, int NOUT, bool TRANSW, bool USE_GSEQ, bool HASB>
__global__ __launch_bounds__(512) void gemm_tf32(const float* __restrict__ Xparam,
                                                 const float* __restrict__ Wg,
                                                 const float* __restrict__ bias,
                                                 int Mtotal, int ntiles) {
    extern __shared__ u32 smem[];
    u32* Ws = smem;                                   // NP * KP
    u32* Xs = smem + NP * KP;                         // 128 * KP
    float* bs = (float*)(smem + NP * KP + 128 * KP);  // NP

    const float* X = USE_GSEQ ? (const float*)g_seq : Xparam;
    float* out = USE_GSEQ ? (float*)g_GX : (float*)g_T;

    int tid = threadIdx.x;
    int w = tid >> 5, lane = tid & 31;
    int mw = w & 3, nw = w >> 2;
    int g = lane >> 2, tig = lane & 3;
    int colbase = nw * NFR * 8;

    // --- Stage W (once per block), paired layout ---
    for (int i = tid; i < NP * KP; i += 512) {
        int n = i / KP, k = i % KP;
        float v = 0.f;
        if (n < NOUT && k < HID_)
            v = TRANSW ? Wg[k * NOUT + n] : Wg[n * HID_ + k];
        Ws[n * KP + kidx(k)] = f2tf(v);
    }
    for (int i = tid; i < NP; i += 512)
        bs[i] = (HASB && i < NOUT) ? bias[i] : 0.f;
    __syncthreads();

    for (int tile = blockIdx.x; tile < ntiles; tile += gridDim.x) {
        __syncthreads();   // previous tile's Xs fully consumed
        // X staging: float4 gmem reads, scattered STS into paired layout.
        for (int i = tid; i < 128 * 26; i += 512) {
            int m = i / 26, c = i % 26;
            u32* rowp = Xs + m * KP;
            if (c < 25) {
                int row = tile * 128 + m;
                float4 v = make_float4(0.f, 0.f, 0.f, 0.f);
                if (row < Mtotal) v = ((const float4*)X)[(size_t)row * 25 + c];
                int base = ((c >> 1) << 3) + (c & 1);
                rowp[base]     = f2tf(v.x);
                rowp[base + 2] = f2tf(v.y);
                rowp[base + 4] = f2tf(v.z);
                rowp[base + 6] = f2tf(v.w);
            } else {
                rowp[97] = 0u; rowp[99] = 0u; rowp[101] = 0u; rowp[103] = 0u;
            }
        }
        __syncthreads();

        float c[2][NFR][4];
        #pragma unroll
        for (int mb = 0; mb < 2; mb++)
            #pragma unroll
            for (int f = 0; f < NFR; f++) {
                c[mb][f][0] = 0.f; c[mb][f][1] = 0.f;
                c[mb][f][2] = 0.f; c[mb][f][3] = 0.f;
            }

        const u32* Xb0 = Xs + (mw * 16) * KP;
        const u32* Xb1 = Xs + (64 + mw * 16) * KP;
        #pragma unroll
        for (int ks = 0; ks < 13; ks++) {
            int k0 = ks * 8 + 2 * tig;
            uint2 a00 = *(const uint2*)&Xb0[g * KP + k0];        // (a0, a2) mb0
            uint2 a01 = *(const uint2*)&Xb0[(g + 8) * KP + k0];  // (a1, a3) mb0
            uint2 a10 = *(const uint2*)&Xb1[g * KP + k0];        // mb1
            uint2 a11 = *(const uint2*)&Xb1[(g + 8) * KP + k0];
            #pragma unroll
            for (int f = 0; f < NFR; f++) {
                uint2 pb = *(const uint2*)&Ws[(colbase + 8 * f + g) * KP + k0];
                mma1688(c[0][f], a00.x, a01.x, a00.y, a01.y, pb.x, pb.y);
                mma1688(c[1][f], a10.x, a11.x, a10.y, a11.y, pb.x, pb.y);
            }
        }

        #pragma unroll
        for (int mb = 0; mb < 2; mb++) {
            int r0 = tile * 128 + mb * 64 + mw * 16 + g;
            #pragma unroll
            for (int f = 0; f < NFR; f++) {
                int col = colbase + 8 * f + 2 * tig;
                if (r0 < Mtotal) {
                    if (col < NOUT)     out[(size_t)r0 * NOUT + col]     = c[mb][f][0] + bs[col];
                    if (col + 1 < NOUT) out[(size_t)r0 * NOUT + col + 1] = c[mb][f][1] + bs[col + 1];
                }
                if (r0 + 8 < Mtotal) {
                    if (col < NOUT)     out[(size_t)(r0 + 8) * NOUT + col]     = c[mb][f][2] + bs[col];
                    if (col + 1 < NOUT) out[(size_t)(r0 + 8) * NOUT + col + 1] = c[mb][f][3] + bs[col + 1];
                }
            }
        }
    }
}

#define K1_SMEM ((128 * KP + 128 * KP) * 4 + 128 * 4)
#define K4_SMEM ((320 * KP + 128 * KP) * 4 + 320 * 4)

// ---------------------------------------------------------------------------
// K2: per-batch counting sort of edges by row (histogram + scan + scatter)
// ---------------------------------------------------------------------------
__global__ __launch_bounds__(1024) void k2_sort(const int* __restrict__ row,
                                                const int* __restrict__ col,
                                                const float* __restrict__ val) {
    __shared__ int bins[N_];
    __shared__ int sA[N_];
    int b = blockIdx.x, tid = threadIdx.x;
    bins[tid] = 0;
    __syncthreads();
    const int* rb = row + b * E_;
    const int* cb = col + b * E_;
    const float* vb = val + b * E_;
    for (int e = tid; e < E_; e += 1024) atomicAdd(&bins[rb[e]], 1);
    __syncthreads();
    int cnt = bins[tid];
    sA[tid] = cnt;
    __syncthreads();
    for (int off = 1; off < N_; off <<= 1) {
        int t = (tid >= off) ? sA[tid - off] : 0;
        __syncthreads();
        sA[tid] += t;
        __syncthreads();
    }
    int excl = sA[tid] - cnt;
    g_soff[b * (N_ + 1) + tid] = excl;
    if (tid == 0) g_soff[b * (N_ + 1) + N_] = E_;
    bins[tid] = excl;
    __syncthreads();
    for (int e = tid; e < E_; e += 1024) {
        int r = rb[e];
        int pos = atomicAdd(&bins[r], 1);
        g_scol[b * E_ + pos] = cb[e];
        g_sval[b * E_ + pos] = vb[e];
    }
}

// ---------------------------------------------------------------------------
// K3: seq[b,r,:] = sum_e val * T[neighbors[b, col_e], :] + gcn_b
// one warp per (b, row); vectorized gather: lane l<25 owns dims [4l,4l+4)
// via LDG.128 (4x fewer load instructions than scalar), STG.128 output.
// 4-edge unroll retained for MLP.
// ---------------------------------------------------------------------------
__global__ __launch_bounds__(256) void k3_agg(const int* __restrict__ nbr,
                                              const float* __restrict__ gcn_b) {
    int b = blockIdx.x;
    int rbase = blockIdx.y * 64;
    int warp = threadIdx.x >> 5, lane = threadIdx.x & 31;
    const int* sc = g_scol + b * E_;
    const float* sv = g_sval + b * E_;
    const int* nb = nbr + b * N_;
    bool ld = lane < 25;
    float4 bb = make_float4(0.f, 0.f, 0.f, 0.f);
    if (ld) bb = ((const float4*)gcn_b)[lane];
    for (int r = rbase + warp; r < rbase + 64; r += 8) {
        int beg = g_soff[b * (N_ + 1) + r], end = g_soff[b * (N_ + 1) + r + 1];
        float4 acc0 = make_float4(0.f, 0.f, 0.f, 0.f);
        float4 acc1 = make_float4(0.f, 0.f, 0.f, 0.f);
        for (int ch = beg; ch < end; ch += 32) {
            int e = ch + lane;
            int cc = 0; float vv = 0.f;
            if (e < end) { cc = sc[e]; vv = sv[e]; }
            int ent = nb[cc];
            int cnt = min(32, end - ch);
            int i = 0;
            for (; i + 3 < cnt; i += 4) {
                int e0 = __shfl_sync(0xffffffffu, ent, i);
                int e1 = __shfl_sync(0xffffffffu, ent, i + 1);
                int e2 = __shfl_sync(0xffffffffu, ent, i + 2);
                int e3 = __shfl_sync(0xffffffffu, ent, i + 3);
                float v0 = __shfl_sync(0xffffffffu, vv, i);
                float v1 = __shfl_sync(0xffffffffu, vv, i + 1);
                float v2 = __shfl_sync(0xffffffffu, vv, i + 2);
                float v3 = __shfl_sync(0xffffffffu, vv, i + 3);
                if (ld) {
                    float4 x0 = *(const float4*)(g_T + (size_t)e0 * HID_ + 4 * lane);
                    float4 x1 = *(const float4*)(g_T + (size_t)e1 * HID_ + 4 * lane);
                    float4 x2 = *(const float4*)(g_T + (size_t)e2 * HID_ + 4 * lane);
                    float4 x3 = *(const float4*)(g_T + (size_t)e3 * HID_ + 4 * lane);
                    acc0.x += v0 * x0.x; acc0.y += v0 * x0.y; acc0.z += v0 * x0.z; acc0.w += v0 * x0.w;
                    acc1.x += v1 * x1.x; acc1.y += v1 * x1.y; acc1.z += v1 * x1.z; acc1.w += v1 * x1.w;
                    acc0.x += v2 * x2.x; acc0.y += v2 * x2.y; acc0.z += v2 * x2.z; acc0.w += v2 * x2.w;
                    acc1.x += v3 * x3.x; acc1.y += v3 * x3.y; acc1.z += v3 * x3.z; acc1.w += v3 * x3.w;
                }
            }
            for (; i < cnt; i++) {
                int e0 = __shfl_sync(0xffffffffu, ent, i);
                float v0 = __shfl_sync(0xffffffffu, vv, i);
                if (ld) {
                    float4 x0 = *(const float4*)(g_T + (size_t)e0 * HID_ + 4 * lane);
                    acc0.x += v0 * x0.x; acc0.y += v0 * x0.y; acc0.z += v0 * x0.z; acc0.w += v0 * x0.w;
                }
            }
        }
        if (ld) {
            float4 o;
            o.x = acc0.x + acc1.x + bb.x;
            o.y = acc0.y + acc1.y + bb.y;
            o.z = acc0.z + acc1.z + bb.z;
            o.w = acc0.w + acc1.w + bb.w;
            *(float4*)(g_seq + (size_t)(b * N_ + r) * HID_ + 4 * lane) = o;
        }
    }
}

// ---------------------------------------------------------------------------
// K5: GRU recurrence, one block per batch element; HW tanh.approx activations.
// ---------------------------------------------------------------------------
__global__ __launch_bounds__(320) void k5_gru(const float* __restrict__ w_hh,
                                              const float* __restrict__ b_hh,
                                              const float* __restrict__ fc1_w,
                                              const float* __restrict__ fc1_b,
                                              float* __restrict__ out) {
    __shared__ __align__(16) float hbuf[2][128];
    __shared__ float ghs[G3];
    __shared__ float ring[8][G3];
    int b = blockIdx.x, tid = threadIdx.x;
    int j = tid;
    bool act = j < G3;
    u64 w2[50];
    float bhh = 0.f;
    if (act) {
        const u64* wp = (const u64*)(w_hh + j * HID_);
        #pragma unroll
        for (int p = 0; p < 50; p++) w2[p] = wp[p];
        bhh = b_hh[j];
    }
    if (tid < 128) { hbuf[0][tid] = 0.f; hbuf[1][tid] = 0.f; }
    const float* gxb = g_GX + (size_t)b * N_ * G3;
    #pragma unroll
    for (int p = 0; p < 4; p++) {
        if (act) cp4(&ring[p][j], gxb + p * G3 + j);
        asm volatile("cp.async.commit_group;");
    }
    for (int t = 0; t < N_; t++) {
        asm volatile("cp.async.wait_group 3;");
        __syncthreads();
        int pf = t + 4;
        if (act && pf < N_) cp4(&ring[pf & 7][j], gxb + (size_t)pf * G3 + j);
        asm volatile("cp.async.commit_group;");
        const float* hc = hbuf[t & 1];
        if (act) {
            const ulonglong2* hp = (const ulonglong2*)hc;
            u64 a0 = 0, a1 = 0, a2 = 0, a3 = 0;
            #pragma unroll
            for (int qq = 0; qq < 25; qq++) {
                ulonglong2 hv = hp[qq];
                if (qq & 1) { ffma2(a2, w2[2 * qq], hv.x); ffma2(a3, w2[2 * qq + 1], hv.y); }
                else        { ffma2(a0, w2[2 * qq], hv.x); ffma2(a1, w2[2 * qq + 1], hv.y); }
            }
            ghs[j] = sum2(a0) + sum2(a1) + sum2(a2) + sum2(a3) + bhh;
        }
        __syncthreads();
        if (j < HID_) {
            int st = t & 7;
            float gxr = ring[st][j], gxz = ring[st][HID_ + j], gxn = ring[st][2 * HID_ + j];
            float hr = ghs[j], hz = ghs[HID_ + j], hn = ghs[2 * HID_ + j];
            float r = 0.5f * tanhapx(0.5f * (gxr + hr)) + 0.5f;
            float z = 0.5f * tanhapx(0.5f * (gxz + hz)) + 0.5f;
            float n = tanhapx(gxn + r * hn);
            hbuf[(t + 1) & 1][j] = (1.f - z) * n + z * hc[j];
        }
    }
    __syncthreads();
    if (j < HID_) {
        const float* hf = hbuf[0];
        float acc = fc1_b[j];
        const float* wr = fc1_w + j * HID_;
        #pragma unroll
        for (int k = 0; k < HID_; k++) acc += hf[k] * wr[k];
        out[b * HID_ + j] = fmaxf(acc, 0.f);
    }
}

// ---------------------------------------------------------------------------
extern "C" void kernel_launch(void* const* d_in, const int* in_sizes, int n_in,
                              void* d_out, int out_size) {
    const int*   neighbors = (const int*)d_in[0];
    const int*   adj_row   = (const int*)d_in[1];
    const int*   adj_col   = (const int*)d_in[2];
    const float* adj_val   = (const float*)d_in[3];
    const float* emb       = (const float*)d_in[4];
    const float* gcn_w     = (const float*)d_in[5];
    const float* gcn_b     = (const float*)d_in[6];
    const float* w_ih      = (const float*)d_in[7];
    const float* w_hh      = (const float*)d_in[8];
    const float* b_ih      = (const float*)d_in[9];
    const float* b_hh      = (const float*)d_in[10];
    const float* fc1_w     = (const float*)d_in[11];
    const float* fc1_b     = (const float*)d_in[12];
    float* out = (float*)d_out;

    cudaFuncSetAttribute(gemm_tf32<128, 4, 100, true, false, false>,
                         cudaFuncAttributeMaxDynamicSharedMemorySize, K1_SMEM);
    cudaFuncSetAttribute(gemm_tf32<320, 10, 300, false, true, true>,
                         cudaFuncAttributeMaxDynamicSharedMemorySize, K4_SMEM);

    // K1: T = emb @ gcn_w  (no bias — gcn_b is added in K3 after the spmm)
    gemm_tf32<128, 4, 100, true, false, false><<<148, 512, K1_SMEM>>>(
        emb, gcn_w, gcn_b, ENTITY_, (ENTITY_ + 127) / 128);
    k2_sort<<<B_, 1024>>>(adj_row, adj_col, adj_val);
    k3_agg <<<dim3(B_, 16), 256>>>(neighbors, gcn_b);
    // K4: GX = seq @ w_ih^T + b_ih
    gemm_tf32<320, 10, 300, false, true, true><<<148, 512, K4_SMEM>>>(
        nullptr, w_ih, b_ih, B_ * N_, (B_ * N_ + 127) / 128);
    k5_gru <<<B_, 320>>>(w_hh, b_hh, fc1_w, fc1_b, out);
}

// round 10
// speedup vs baseline: 1.6810x; 1.0181x over previous
#include <cuda_runtime.h>

#define B_ 128
#define N_ 1024
#define E_ 16384
#define ENTITY_ 100000
#define HID_ 100
#define G3 300

// Scratch (static __device__ per harness rules; no runtime allocation)
__device__ float g_T[ENTITY_ * HID_];        // emb_table @ gcn_w   (40MB)
__device__ float g_seq[B_ * N_ * HID_];      // GCN output          (52MB)
__device__ float g_GX[B_ * N_ * G3];         // seq @ w_ih^T + b_ih (157MB)
__device__ int   g_soff[B_ * (N_ + 1)];
__device__ int   g_scol[B_ * E_];
__device__ float g_sval[B_ * E_];

typedef unsigned long long u64;
typedef unsigned int u32;

__device__ __forceinline__ void ffma2(u64 &acc, u64 a, u64 b) {
    asm("fma.rn.f32x2 %0, %1, %2, %0;" : "+l"(acc) : "l"(a), "l"(b));
}
__device__ __forceinline__ float sum2(u64 v) {
    float lo, hi; asm("mov.b64 {%0, %1}, %2;" : "=f"(lo), "=f"(hi) : "l"(v)); return lo + hi;
}
__device__ __forceinline__ void cp4(void* s, const void* g) {
    unsigned a = (unsigned)__cvta_generic_to_shared(s);
    asm volatile("cp.async.ca.shared.global [%0], [%1], 4;" :: "r"(a), "l"(g));
}
__device__ __forceinline__ u32 f2tf(float x) {
    u32 r; asm("cvt.rna.tf32.f32 %0, %1;" : "=r"(r) : "f"(x)); return r;
}
__device__ __forceinline__ float tanhapx(float x) {
    float r; asm("tanh.approx.f32 %0, %1;" : "=f"(r) : "f"(x)); return r;
}
__device__ __forceinline__ void mma1688(float c[4], u32 a0, u32 a1, u32 a2, u32 a3,
                                        u32 b0, u32 b1) {
    asm("mma.sync.aligned.m16n8k8.row.col.f32.tf32.tf32.f32 "
        "{%0,%1,%2,%3}, {%4,%5,%6,%7}, {%8,%9}, {%0,%1,%2,%3};"
        : "+f"(c[0]), "+f"(c[1]), "+f"(c[2]), "+f"(c[3])
        : "r"(a0), "r"(a1), "r"(a2), "r"(a3), "r"(b0), "r"(b1));
}

// ---------------------------------------------------------------------------
// tf32 GEMM: out[M x NOUT] = X[M x 100] @ W^T (+ bias if HASB)   [R9 — proven]
// M-tile = 128 rows; 512 threads = 16 warps (4 m-pos x 4 n-groups); W staged
// once per block; k-PAIRED smem layout -> all fragment loads are LDS.64.
// ---------------------------------------------------------------------------
#define KP 104

__device__ __forceinline__ int kidx(int k) {   // paired index within a row
    return ((k >> 3) << 3) + ((k & 3) << 1) + ((k & 7) >> 2);
}

template<int NP, int NFR, int NOUT, bool TRANSW, bool USE_GSEQ, bool HASB>
__global__ __launch_bounds__(512) void gemm_tf32(const float* __restrict__ Xparam,
                                                 const float* __restrict__ Wg,
                                                 const float* __restrict__ bias,
                                                 int Mtotal, int ntiles) {
    extern __shared__ u32 smem[];
    u32* Ws = smem;                                   // NP * KP
    u32* Xs = smem + NP * KP;                         // 128 * KP
    float* bs = (float*)(smem + NP * KP + 128 * KP);  // NP

    const float* X = USE_GSEQ ? (const float*)g_seq : Xparam;
    float* out = USE_GSEQ ? (float*)g_GX : (float*)g_T;

    int tid = threadIdx.x;
    int w = tid >> 5, lane = tid & 31;
    int mw = w & 3, nw = w >> 2;
    int g = lane >> 2, tig = lane & 3;
    int colbase = nw * NFR * 8;

    for (int i = tid; i < NP * KP; i += 512) {
        int n = i / KP, k = i % KP;
        float v = 0.f;
        if (n < NOUT && k < HID_)
            v = TRANSW ? Wg[k * NOUT + n] : Wg[n * HID_ + k];
        Ws[n * KP + kidx(k)] = f2tf(v);
    }
    for (int i = tid; i < NP; i += 512)
        bs[i] = (HASB && i < NOUT) ? bias[i] : 0.f;
    __syncthreads();

    for (int tile = blockIdx.x; tile < ntiles; tile += gridDim.x) {
        __syncthreads();
        for (int i = tid; i < 128 * 26; i += 512) {
            int m = i / 26, c = i % 26;
            u32* rowp = Xs + m * KP;
            if (c < 25) {
                int row = tile * 128 + m;
                float4 v = make_float4(0.f, 0.f, 0.f, 0.f);
                if (row < Mtotal) v = ((const float4*)X)[(size_t)row * 25 + c];
                int base = ((c >> 1) << 3) + (c & 1);
                rowp[base]     = f2tf(v.x);
                rowp[base + 2] = f2tf(v.y);
                rowp[base + 4] = f2tf(v.z);
                rowp[base + 6] = f2tf(v.w);
            } else {
                rowp[97] = 0u; rowp[99] = 0u; rowp[101] = 0u; rowp[103] = 0u;
            }
        }
        __syncthreads();

        float c[2][NFR][4];
        #pragma unroll
        for (int mb = 0; mb < 2; mb++)
            #pragma unroll
            for (int f = 0; f < NFR; f++) {
                c[mb][f][0] = 0.f; c[mb][f][1] = 0.f;
                c[mb][f][2] = 0.f; c[mb][f][3] = 0.f;
            }

        const u32* Xb0 = Xs + (mw * 16) * KP;
        const u32* Xb1 = Xs + (64 + mw * 16) * KP;
        #pragma unroll
        for (int ks = 0; ks < 13; ks++) {
            int k0 = ks * 8 + 2 * tig;
            uint2 a00 = *(const uint2*)&Xb0[g * KP + k0];
            uint2 a01 = *(const uint2*)&Xb0[(g + 8) * KP + k0];
            uint2 a10 = *(const uint2*)&Xb1[g * KP + k0];
            uint2 a11 = *(const uint2*)&Xb1[(g + 8) * KP + k0];
            #pragma unroll
            for (int f = 0; f < NFR; f++) {
                uint2 pb = *(const uint2*)&Ws[(colbase + 8 * f + g) * KP + k0];
                mma1688(c[0][f], a00.x, a01.x, a00.y, a01.y, pb.x, pb.y);
                mma1688(c[1][f], a10.x, a11.x, a10.y, a11.y, pb.x, pb.y);
            }
        }

        #pragma unroll
        for (int mb = 0; mb < 2; mb++) {
            int r0 = tile * 128 + mb * 64 + mw * 16 + g;
            #pragma unroll
            for (int f = 0; f < NFR; f++) {
                int col = colbase + 8 * f + 2 * tig;
                if (r0 < Mtotal) {
                    if (col < NOUT)     out[(size_t)r0 * NOUT + col]     = c[mb][f][0] + bs[col];
                    if (col + 1 < NOUT) out[(size_t)r0 * NOUT + col + 1] = c[mb][f][1] + bs[col + 1];
                }
                if (r0 + 8 < Mtotal) {
                    if (col < NOUT)     out[(size_t)(r0 + 8) * NOUT + col]     = c[mb][f][2] + bs[col];
                    if (col + 1 < NOUT) out[(size_t)(r0 + 8) * NOUT + col + 1] = c[mb][f][3] + bs[col + 1];
                }
            }
        }
    }
}

#define K1_SMEM ((128 * KP + 128 * KP) * 4 + 128 * 4)
#define K4_SMEM ((320 * KP + 128 * KP) * 4 + 320 * 4)

// ---------------------------------------------------------------------------
// K2: per-batch counting sort of edges by row (histogram + scan + scatter)
// ---------------------------------------------------------------------------
__global__ __launch_bounds__(1024) void k2_sort(const int* __restrict__ row,
                                                const int* __restrict__ col,
                                                const float* __restrict__ val) {
    __shared__ int bins[N_];
    __shared__ int sA[N_];
    int b = blockIdx.x, tid = threadIdx.x;
    bins[tid] = 0;
    __syncthreads();
    const int* rb = row + b * E_;
    const int* cb = col + b * E_;
    const float* vb = val + b * E_;
    for (int e = tid; e < E_; e += 1024) atomicAdd(&bins[rb[e]], 1);
    __syncthreads();
    int cnt = bins[tid];
    sA[tid] = cnt;
    __syncthreads();
    for (int off = 1; off < N_; off <<= 1) {
        int t = (tid >= off) ? sA[tid - off] : 0;
        __syncthreads();
        sA[tid] += t;
        __syncthreads();
    }
    int excl = sA[tid] - cnt;
    g_soff[b * (N_ + 1) + tid] = excl;
    if (tid == 0) g_soff[b * (N_ + 1) + N_] = E_;
    bins[tid] = excl;
    __syncthreads();
    for (int e = tid; e < E_; e += 1024) {
        int r = rb[e];
        int pos = atomicAdd(&bins[r], 1);
        g_scol[b * E_ + pos] = cb[e];
        g_sval[b * E_ + pos] = vb[e];
    }
}

// ---------------------------------------------------------------------------
// K3: seq[b,r,:] = sum_e val * T[neighbors[b, col_e], :] + gcn_b
// one warp per (b, row); lane l<25 owns dims [4l,4l+4) via LDG.128. [R9]
// ---------------------------------------------------------------------------
__global__ __launch_bounds__(256) void k3_agg(const int* __restrict__ nbr,
                                              const float* __restrict__ gcn_b) {
    int b = blockIdx.x;
    int rbase = blockIdx.y * 64;
    int warp = threadIdx.x >> 5, lane = threadIdx.x & 31;
    const int* sc = g_scol + b * E_;
    const float* sv = g_sval + b * E_;
    const int* nb = nbr + b * N_;
    bool ld = lane < 25;
    float4 bb = make_float4(0.f, 0.f, 0.f, 0.f);
    if (ld) bb = ((const float4*)gcn_b)[lane];
    for (int r = rbase + warp; r < rbase + 64; r += 8) {
        int beg = g_soff[b * (N_ + 1) + r], end = g_soff[b * (N_ + 1) + r + 1];
        float4 acc0 = make_float4(0.f, 0.f, 0.f, 0.f);
        float4 acc1 = make_float4(0.f, 0.f, 0.f, 0.f);
        for (int ch = beg; ch < end; ch += 32) {
            int e = ch + lane;
            int cc = 0; float vv = 0.f;
            if (e < end) { cc = sc[e]; vv = sv[e]; }
            int ent = nb[cc];
            int cnt = min(32, end - ch);
            int i = 0;
            for (; i + 3 < cnt; i += 4) {
                int e0 = __shfl_sync(0xffffffffu, ent, i);
                int e1 = __shfl_sync(0xffffffffu, ent, i + 1);
                int e2 = __shfl_sync(0xffffffffu, ent, i + 2);
                int e3 = __shfl_sync(0xffffffffu, ent, i + 3);
                float v0 = __shfl_sync(0xffffffffu, vv, i);
                float v1 = __shfl_sync(0xffffffffu, vv, i + 1);
                float v2 = __shfl_sync(0xffffffffu, vv, i + 2);
                float v3 = __shfl_sync(0xffffffffu, vv, i + 3);
                if (ld) {
                    float4 x0 = *(const float4*)(g_T + (size_t)e0 * HID_ + 4 * lane);
                    float4 x1 = *(const float4*)(g_T + (size_t)e1 * HID_ + 4 * lane);
                    float4 x2 = *(const float4*)(g_T + (size_t)e2 * HID_ + 4 * lane);
                    float4 x3 = *(const float4*)(g_T + (size_t)e3 * HID_ + 4 * lane);
                    acc0.x += v0 * x0.x; acc0.y += v0 * x0.y; acc0.z += v0 * x0.z; acc0.w += v0 * x0.w;
                    acc1.x += v1 * x1.x; acc1.y += v1 * x1.y; acc1.z += v1 * x1.z; acc1.w += v1 * x1.w;
                    acc0.x += v2 * x2.x; acc0.y += v2 * x2.y; acc0.z += v2 * x2.z; acc0.w += v2 * x2.w;
                    acc1.x += v3 * x3.x; acc1.y += v3 * x3.y; acc1.z += v3 * x3.z; acc1.w += v3 * x3.w;
                }
            }
            for (; i < cnt; i++) {
                int e0 = __shfl_sync(0xffffffffu, ent, i);
                float v0 = __shfl_sync(0xffffffffu, vv, i);
                if (ld) {
                    float4 x0 = *(const float4*)(g_T + (size_t)e0 * HID_ + 4 * lane);
                    acc0.x += v0 * x0.x; acc0.y += v0 * x0.y; acc0.z += v0 * x0.z; acc0.w += v0 * x0.w;
                }
            }
        }
        if (ld) {
            float4 o;
            o.x = acc0.x + acc1.x + bb.x;
            o.y = acc0.y + acc1.y + bb.y;
            o.z = acc0.z + acc1.z + bb.z;
            o.w = acc0.w + acc1.w + bb.w;
            *(float4*)(g_seq + (size_t)(b * N_ + r) * HID_ + 4 * lane) = o;
        }
    }
}

// ---------------------------------------------------------------------------
// K5: GRU recurrence, one block per batch; k-SPLIT x2: thread = (k-half q,
// gate j). Each thread runs half the dot product (13 LDS.128 + 26 FFMA2)
// into ps[q][j]; activation combines. Halves the per-step serial chain and
// raises warps/SM 10 -> 19. k-halves padded to 52 floats (16B-aligned for
// q=1; pad slots zeroed once, never rewritten). HW tanh.approx activations.
// ---------------------------------------------------------------------------
__global__ __launch_bounds__(608) void k5_gru(const float* __restrict__ w_hh,
                                              const float* __restrict__ b_hh,
                                              const float* __restrict__ fc1_w,
                                              const float* __restrict__ fc1_b,
                                              float* __restrict__ out) {
    __shared__ __align__(16) float hbuf[2][128];   // [0..99] h, [100..103] zero pad
    __shared__ float ps[2][304];
    __shared__ float ring[8][G3];
    int b = blockIdx.x, tid = threadIdx.x;
    int q = tid / 304;          // k-half
    int j = tid % 304;          // gate index, <300 active
    bool act = j < G3;
    u64 w2[26];
    if (act) {
        #pragma unroll
        for (int p = 0; p < 26; p++) {
            int k = 52 * q + 2 * p;
            w2[p] = (k + 1 < HID_) ? *(const u64*)(w_hh + j * HID_ + k) : 0ull;
        }
    }
    float br = 0.f, bz = 0.f, bn = 0.f;
    if (tid < HID_) {
        br = b_hh[tid]; bz = b_hh[HID_ + tid]; bn = b_hh[2 * HID_ + tid];
    }
    if (tid < 128) { hbuf[0][tid] = 0.f; hbuf[1][tid] = 0.f; }
    const float* gxb = g_GX + (size_t)b * N_ * G3;
    #pragma unroll
    for (int p = 0; p < 4; p++) {
        if (tid < G3) cp4(&ring[p][tid], gxb + p * G3 + tid);
        asm volatile("cp.async.commit_group;");
    }
    for (int t = 0; t < N_; t++) {
        asm volatile("cp.async.wait_group 3;");
        __syncthreads();                     // stage-t ring + new h visible
        int pf = t + 4;
        if (tid < G3 && pf < N_) cp4(&ring[pf & 7][tid], gxb + (size_t)pf * G3 + tid);
        asm volatile("cp.async.commit_group;");
        const float* hc = hbuf[t & 1];
        if (act) {
            const ulonglong2* hp = (const ulonglong2*)(hc + 52 * q);
            u64 a0 = 0, a1 = 0, a2 = 0, a3 = 0;
            #pragma unroll
            for (int cc = 0; cc < 13; cc++) {
                ulonglong2 hv = hp[cc];
                if (cc & 1) { ffma2(a2, w2[2 * cc], hv.x); ffma2(a3, w2[2 * cc + 1], hv.y); }
                else        { ffma2(a0, w2[2 * cc], hv.x); ffma2(a1, w2[2 * cc + 1], hv.y); }
            }
            ps[q][j] = sum2(a0) + sum2(a1) + sum2(a2) + sum2(a3);
        }
        __syncthreads();                     // partials ready
        if (tid < HID_) {
            int st = t & 7;
            float gxr = ring[st][tid], gxz = ring[st][HID_ + tid], gxn = ring[st][2 * HID_ + tid];
            float hr = ps[0][tid] + ps[1][tid] + br;
            float hz = ps[0][HID_ + tid] + ps[1][HID_ + tid] + bz;
            float hn = ps[0][2 * HID_ + tid] + ps[1][2 * HID_ + tid] + bn;
            float r = 0.5f * tanhapx(0.5f * (gxr + hr)) + 0.5f;
            float z = 0.5f * tanhapx(0.5f * (gxz + hz)) + 0.5f;
            float n = tanhapx(gxn + r * hn);
            hbuf[(t + 1) & 1][tid] = (1.f - z) * n + z * hc[tid];
        }
    }
    __syncthreads();
    if (tid < HID_) {
        const float* hf = hbuf[0];           // t=1023 wrote buffer 0
        float acc = fc1_b[tid];
        const float* wr = fc1_w + tid * HID_;
        #pragma unroll
        for (int k = 0; k < HID_; k++) acc += hf[k] * wr[k];
        out[b * HID_ + tid] = fmaxf(acc, 0.f);
    }
}

// ---------------------------------------------------------------------------
extern "C" void kernel_launch(void* const* d_in, const int* in_sizes, int n_in,
                              void* d_out, int out_size) {
    const int*   neighbors = (const int*)d_in[0];
    const int*   adj_row   = (const int*)d_in[1];
    const int*   adj_col   = (const int*)d_in[2];
    const float* adj_val   = (const float*)d_in[3];
    const float* emb       = (const float*)d_in[4];
    const float* gcn_w     = (const float*)d_in[5];
    const float* gcn_b     = (const float*)d_in[6];
    const float* w_ih      = (const float*)d_in[7];
    const float* w_hh      = (const float*)d_in[8];
    const float* b_ih      = (const float*)d_in[9];
    const float* b_hh      = (const float*)d_in[10];
    const float* fc1_w     = (const float*)d_in[11];
    const float* fc1_b     = (const float*)d_in[12];
    float* out = (float*)d_out;

    cudaFuncSetAttribute(gemm_tf32<128, 4, 100, true, false, false>,
                         cudaFuncAttributeMaxDynamicSharedMemorySize, K1_SMEM);
    cudaFuncSetAttribute(gemm_tf32<320, 10, 300, false, true, true>,
                         cudaFuncAttributeMaxDynamicSharedMemorySize, K4_SMEM);

    // K1: T = emb @ gcn_w  (no bias — gcn_b is added in K3 after the spmm)
    gemm_tf32<128, 4, 100, true, false, false><<<148, 512, K1_SMEM>>>(
        emb, gcn_w, gcn_b, ENTITY_, (ENTITY_ + 127) / 128);
    k2_sort<<<B_, 1024>>>(adj_row, adj_col, adj_val);
    k3_agg <<<dim3(B_, 16), 256>>>(neighbors, gcn_b);
    // K4: GX = seq @ w_ih^T + b_ih
    gemm_tf32<320, 10, 300, false, true, true><<<148, 512, K4_SMEM>>>(
        nullptr, w_ih, b_ih, B_ * N_, (B_ * N_ + 127) / 128);
    k5_gru <<<B_, 608>>>(w_hh, b_hh, fc1_w, fc1_b, out);
}